// round 9
// baseline (speedup 1.0000x reference)
#include <cuda_runtime.h>
#include <cuda_bf16.h>

// Problem constants
#define BATCH    1024
#define P784     784
#define CATW     848            // 784 + 32 + 32
#define OUTF     32
#define STEPS    32

// Scratch (allocation-free rule: __device__ globals)
__device__ float g_cat [BATCH * CATW];   // [1024, 848] concat rows
__device__ float g_zacc[BATCH * 64];     // fc1 pre-activation accumulator

// ---------------------------------------------------------------------------
// Kernel 1: per-sample fused conv branch + landscape branches.
//   grid = 1024 blocks (1 per sample), 256 threads.
//   conv: double-buffered single-channel tile in smem, 1x4 register tiles.
//   landscape: tent(v,t) is monotone non-increasing in v => top-2 tents come
//   from the two SMALLEST filtration values; only (min1,min2,max) needed.
// ---------------------------------------------------------------------------
__global__ void __launch_bounds__(256)
k_fused(const float* __restrict__ x,
        const float* __restrict__ dtm1,
        const float* __restrict__ dtm2,
        const float* __restrict__ w1g, const float* __restrict__ b1g,
        const float* __restrict__ w2g, const float* __restrict__ b2g,
        const float* __restrict__ g1w, const float* __restrict__ g1b,
        const float* __restrict__ g2w, const float* __restrict__ g2b)
{
    __shared__ __align__(16) float w1t[32][12];   // [channel][tap 0..8], padded
    __shared__ __align__(16) float w2t[32][12];
    __shared__ float b1s[32];
    __shared__ __align__(16) float sx[30][32];    // input with zero halo
    __shared__ __align__(16) float tb[2][30][32]; // per-channel conv1 tile, halo'd, dbl-buffered
    __shared__ float Ls[2][64];                   // landscapes
    __shared__ float red1[8], red2[8], red3[8];
    __shared__ float stats[2][3];                 // (min1, min2, max) per branch

    const int tid = threadIdx.x;
    const int b   = blockIdx.x;

    // zero the fc1 accumulator row for this sample (consumed by k_fc1 later)
    if (tid < 64) g_zacc[b * 64 + tid] = 0.f;

    // ---- load weights (transposed, taps contiguous per channel) ----
    for (int i = tid; i < 288; i += 256) {
        int tap = i / 32, c = i % 32;
        w1t[c][tap] = w1g[i];
        w2t[c][tap] = w2g[i];
    }
    if (tid < 32) b1s[tid] = b1g[tid];
    // zero tile buffers (halo cells stay zero forever; interior overwritten)
    for (int i = tid; i < 2 * 30 * 32; i += 256) ((float*)tb)[i] = 0.f;
    // stage input with zero halo
    for (int i = tid; i < 900; i += 256) {
        int yy = i / 30, xx = i % 30;
        int ry = yy - 1, cx = xx - 1;
        float v = 0.f;
        if (ry >= 0 && ry < 28 && cx >= 0 && cx < 28) v = x[b * P784 + ry * 28 + cx];
        sx[yy][xx] = v;
    }
    __syncthreads();

    const float b2v = b2g[0];

    // ---- conv phase: 196 active threads, each owns a 1x4 output strip ----
    const bool active = (tid < 196);
    int y = 0, x0 = 0;
    float sxr[3][6];
    float acc[4] = {b2v, b2v, b2v, b2v};
    if (active) {
        y  = tid / 7;
        x0 = (tid % 7) * 4;
        #pragma unroll
        for (int r = 0; r < 3; r++)
            #pragma unroll
            for (int cc = 0; cc < 6; cc++)
                sxr[r][cc] = sx[y + r][x0 + cc];   // = x_pad(y-1+r, x0-1+cc)
    }

    // conv1 for channel c -> t4[0..3] (relu'd)
    auto conv1c = [&](int c, float t4[4]) {
        float4 wa = *(const float4*)&w1t[c][0];
        float4 wb = *(const float4*)&w1t[c][4];
        float  w8 = w1t[c][8];
        float  bc = b1s[c];
        float wv[9] = {wa.x, wa.y, wa.z, wa.w, wb.x, wb.y, wb.z, wb.w, w8};
        #pragma unroll
        for (int j = 0; j < 4; j++) {
            float s = bc;
            #pragma unroll
            for (int dy = 0; dy < 3; dy++)
                #pragma unroll
                for (int dx = 0; dx < 3; dx++)
                    s += sxr[dy][j + dx] * wv[dy * 3 + dx];
            t4[j] = fmaxf(s, 0.f);
        }
    };

    // conv2 accumulation of channel c from buffer `buf`
    auto conv2acc = [&](int c, int buf) {
        float4 wa = *(const float4*)&w2t[c][0];
        float4 wb = *(const float4*)&w2t[c][4];
        float  w8 = w2t[c][8];
        float wv[9] = {wa.x, wa.y, wa.z, wa.w, wb.x, wb.y, wb.z, wb.w, w8};
        #pragma unroll
        for (int dy = 0; dy < 3; dy++) {
            float4 ta = *(const float4*)&tb[buf][y + dy][x0];
            float2 tc = *(const float2*)&tb[buf][y + dy][x0 + 4];
            float tr[6] = {ta.x, ta.y, ta.z, ta.w, tc.x, tc.y};
            #pragma unroll
            for (int dx = 0; dx < 3; dx++) {
                float w = wv[dy * 3 + dx];
                #pragma unroll
                for (int j = 0; j < 4; j++)
                    acc[j] += tr[j + dx] * w;
            }
        }
    };

    // prologue: channel 0 into buffer 0
    if (active) {
        float t4[4];
        conv1c(0, t4);
        #pragma unroll
        for (int j = 0; j < 4; j++) tb[0][y + 1][x0 + 1 + j] = t4[j];
    }
    __syncthreads();

    #pragma unroll 2
    for (int c = 0; c < 32; c++) {
        if (active) {
            if (c < 31) {
                float n4[4];
                conv1c(c + 1, n4);
                int nb = (c + 1) & 1;
                #pragma unroll
                for (int j = 0; j < 4; j++) tb[nb][y + 1][x0 + 1 + j] = n4[j];
            }
            conv2acc(c, c & 1);
        }
        __syncthreads();
    }

    if (active) {
        #pragma unroll
        for (int j = 0; j < 4; j++)
            g_cat[b * CATW + y * 28 + x0 + j] = fmaxf(acc[j], 0.f);
    }

    // ---- landscape branches: (min1, min2, max) reductions ----
    #pragma unroll
    for (int br = 0; br < 2; br++) {
        const float* v = (br == 0 ? dtm1 : dtm2) + b * P784;
        float m1 = 1e30f, m2 = 1e30f, mx = -1e30f;
        for (int i = tid; i < P784; i += 256) {
            float f = v[i];
            mx = fmaxf(mx, f);
            if (f < m1) { m2 = m1; m1 = f; }
            else        { m2 = fminf(m2, f); }
        }
        #pragma unroll
        for (int o = 16; o > 0; o >>= 1) {
            float o1 = __shfl_down_sync(0xffffffffu, m1, o);
            float o2 = __shfl_down_sync(0xffffffffu, m2, o);
            float ox = __shfl_down_sync(0xffffffffu, mx, o);
            float nm1 = fminf(m1, o1);
            float nm2 = fminf(fmaxf(m1, o1), fminf(m2, o2));
            m1 = nm1; m2 = nm2; mx = fmaxf(mx, ox);
        }
        int w = tid >> 5, lane = tid & 31;
        if (lane == 0) { red1[w] = m1; red2[w] = m2; red3[w] = mx; }
        __syncthreads();
        if (w == 0) {
            m1 = (lane < 8) ? red1[lane] : 1e30f;
            m2 = (lane < 8) ? red2[lane] : 1e30f;
            mx = (lane < 8) ? red3[lane] : -1e30f;
            #pragma unroll
            for (int o = 4; o > 0; o >>= 1) {
                float o1 = __shfl_down_sync(0xffffffffu, m1, o);
                float o2 = __shfl_down_sync(0xffffffffu, m2, o);
                float ox = __shfl_down_sync(0xffffffffu, mx, o);
                float nm1 = fminf(m1, o1);
                float nm2 = fminf(fmaxf(m1, o1), fminf(m2, o2));
                m1 = nm1; m2 = nm2; mx = fmaxf(mx, ox);
            }
            if (lane == 0) { stats[br][0] = m1; stats[br][1] = m2; stats[br][2] = mx; }
        }
        __syncthreads();
    }

    // tents: L[br][k*32 + t]
    if (tid < 128) {
        int br = tid >> 6, i = tid & 63;
        int k = i >> 5, ti = i & 31;
        float t0 = (br == 0) ? 0.01f : 0.05f;
        float dt = (br == 0) ? (0.28f / 31.0f) : (0.25f / 31.0f);
        float t  = t0 + (float)ti * dt;
        float vk = k ? stats[br][1] : stats[br][0];
        float d  = stats[br][2];
        Ls[br][i] = fmaxf(0.f, fminf(t - vk, d - t));
    }
    __syncthreads();

    // branch GEMMs: [64] @ [64,32] + bias, relu
    if (tid < 64) {
        int br = tid >> 5, f = tid & 31;
        const float* gw = br ? g2w : g1w;
        float s = br ? g2b[f] : g1b[f];
        #pragma unroll
        for (int j = 0; j < 64; j++) s += Ls[br][j] * gw[j * 32 + f];
        g_cat[b * CATW + 784 + br * 32 + f] = fmaxf(s, 0.f);
    }
}

// ---------------------------------------------------------------------------
// Kernel 2: fc1 as split-K GEMM.  [1024,848] @ [848,64] -> atomicAdd to g_zacc
//   grid = (16 m-tiles of 64) x (8 k-chunks of 106); 256 thr; 4x4 thread tiles.
// ---------------------------------------------------------------------------
__global__ void __launch_bounds__(256)
k_fc1(const float* __restrict__ W1)
{
    __shared__ __align__(16) float At[53 * 68];  // A^T: [k][m], stride 68 (aligned, low conflict)
    __shared__ __align__(16) float Bs[53 * 64];  // [k][f]

    const int tid = threadIdx.x;
    const int m0  = blockIdx.x * 64;
    const int k0  = blockIdx.y * 106;
    const int tm  = tid & 15;   // m-tile index (x4)
    const int tf  = tid >> 4;   // f-tile index (x4)

    float c[4][4] = {};

    #pragma unroll
    for (int sub = 0; sub < 2; sub++) {
        int kb = k0 + sub * 53;
        // A: coalesced row loads, transposed store
        for (int e = tid; e < 53 * 64; e += 256) {
            int i = e / 53, j = e - i * 53;
            At[j * 68 + i] = g_cat[(m0 + i) * CATW + kb + j];
        }
        // B: vectorized
        for (int e = tid; e < 53 * 16; e += 256) {
            int j = e >> 4, q = e & 15;
            *(float4*)&Bs[j * 64 + q * 4] = *(const float4*)&W1[(kb + j) * 64 + q * 4];
        }
        __syncthreads();

        #pragma unroll 4
        for (int k = 0; k < 53; k++) {
            float4 a  = *(const float4*)&At[k * 68 + tm * 4];
            float4 bb = *(const float4*)&Bs[k * 64 + tf * 4];
            float av[4] = {a.x, a.y, a.z, a.w};
            float bv[4] = {bb.x, bb.y, bb.z, bb.w};
            #pragma unroll
            for (int r = 0; r < 4; r++)
                #pragma unroll
                for (int q = 0; q < 4; q++)
                    c[r][q] += av[r] * bv[q];
        }
        __syncthreads();
    }

    #pragma unroll
    for (int r = 0; r < 4; r++)
        #pragma unroll
        for (int q = 0; q < 4; q++)
            atomicAdd(&g_zacc[(m0 + tm * 4 + r) * 64 + tf * 4 + q], c[r][q]);
}

// ---------------------------------------------------------------------------
// Kernel 3: z = relu(zacc + b1); out = z @ W2 + b2.  32 blocks x 32 rows.
// ---------------------------------------------------------------------------
__global__ void __launch_bounds__(256)
k_fc2(const float* __restrict__ fc1b, const float* __restrict__ W2,
      const float* __restrict__ fc2b, float* __restrict__ out)
{
    __shared__ float zs[32 * 64];
    __shared__ float W2s[640];
    __shared__ float b2s[10];

    const int tid = threadIdx.x;
    const int m0  = blockIdx.x * 32;

    for (int e = tid; e < 32 * 64; e += 256) {
        int f = e & 63;
        zs[e] = fmaxf(g_zacc[m0 * 64 + e] + fc1b[f], 0.f);
    }
    for (int e = tid; e < 640; e += 256) W2s[e] = W2[e];
    if (tid < 10) b2s[tid] = fc2b[tid];
    __syncthreads();

    for (int e = tid; e < 320; e += 256) {
        int m = e / 10, cc = e - m * 10;
        float s = b2s[cc];
        #pragma unroll
        for (int f = 0; f < 64; f++) s += zs[m * 64 + f] * W2s[f * 10 + cc];
        out[(m0 + m) * 10 + cc] = s;
    }
}

// ---------------------------------------------------------------------------
extern "C" void kernel_launch(void* const* d_in, const int* in_sizes, int n_in,
                              void* d_out, int out_size)
{
    (void)in_sizes; (void)n_in; (void)out_size;
    const float* x    = (const float*)d_in[0];
    const float* dtm1 = (const float*)d_in[1];
    const float* dtm2 = (const float*)d_in[2];
    const float* w1   = (const float*)d_in[3];
    const float* b1   = (const float*)d_in[4];
    const float* w2   = (const float*)d_in[5];
    const float* b2   = (const float*)d_in[6];
    const float* g1w  = (const float*)d_in[7];
    const float* g1b  = (const float*)d_in[8];
    const float* g2w  = (const float*)d_in[9];
    const float* g2b  = (const float*)d_in[10];
    const float* fc1w = (const float*)d_in[11];
    const float* fc1b = (const float*)d_in[12];
    const float* fc2w = (const float*)d_in[13];
    const float* fc2b = (const float*)d_in[14];
    float* out = (float*)d_out;

    k_fused<<<BATCH, 256>>>(x, dtm1, dtm2, w1, b1, w2, b2, g1w, g1b, g2w, g2b);
    k_fc1<<<dim3(16, 8), 256>>>(fc1w);
    k_fc2<<<32, 256>>>(fc1b, fc2w, fc2b, out);
}

// round 10
// speedup vs baseline: 1.3357x; 1.3357x over previous
#include <cuda_runtime.h>
#include <cuda_bf16.h>

// Problem constants
#define BATCH    1024
#define P784     784
#define CATW     848            // 784 + 32 + 32

// Scratch (allocation-free rule: __device__ globals)
__device__ float g_cat [BATCH * CATW];   // [1024, 848] concat rows
__device__ float g_zacc[BATCH * 64];     // fc1 pre-activation accumulator

// ---------------------------------------------------------------------------
// Kernel 1: per-sample fused conv branch + landscape branches.
//   grid = 1024 blocks (1 per sample), 128 threads (4 warps).
//   Warp w owns output rows [7w, 7w+7); lane = column (lanes 28-31 idle).
//   conv1 -> h1 kept entirely in REGISTERS (9 rows per thread, redundancy 9/7);
//   conv2 column halos come from warp shuffles. No smem tile, no per-channel
//   barriers.
//   landscape: tent(v,t) monotone non-increasing in v => top-2 tents come from
//   the two SMALLEST filtration values; only (min1, min2, max) needed.
// ---------------------------------------------------------------------------
__global__ void __launch_bounds__(128)
k_fused(const float* __restrict__ x,
        const float* __restrict__ dtm1,
        const float* __restrict__ dtm2,
        const float* __restrict__ w1g, const float* __restrict__ b1g,
        const float* __restrict__ w2g, const float* __restrict__ b2g,
        const float* __restrict__ g1w, const float* __restrict__ g1b,
        const float* __restrict__ g2w, const float* __restrict__ g2b)
{
    __shared__ __align__(16) float w1t[32][12];   // [ch][tap0..8, 9=bias]
    __shared__ __align__(16) float w2t[32][12];   // [ch][tap0..8]
    __shared__ float part[2][4][3];               // branch, warp, (m1,m2,mx)
    __shared__ float Ls[2][64];                   // landscapes

    const int tid  = threadIdx.x;
    const int b    = blockIdx.x;
    const int wid  = tid >> 5;
    const int lane = tid & 31;
    const unsigned FULL = 0xffffffffu;

    // zero fc1 accumulator row (consumed by k_fc1)
    if (tid >= 64) g_zacc[b * 64 + (tid - 64)] = 0.f;

    // stage weights transposed: taps contiguous per channel
    for (int i = tid; i < 288; i += 128) {
        int tap = i / 32, c = i % 32;
        w1t[c][tap] = w1g[i];
        w2t[c][tap] = w2g[i];
    }
    if (tid < 32) w1t[tid][9] = b1g[tid];

    // ---- load input rows into registers (rows r0-2 .. r0+8, zero-padded) ----
    const int r0 = wid * 7;
    const int c  = lane;
    float xc[11], xl[11], xr[11];
    #pragma unroll
    for (int j = 0; j < 11; j++) {
        int row = r0 - 2 + j;
        float v = 0.f;
        if (row >= 0 && row < 28 && c < 28) v = x[b * P784 + row * 28 + c];
        xc[j] = v;
    }
    #pragma unroll
    for (int j = 0; j < 11; j++) {
        float u = __shfl_up_sync  (FULL, xc[j], 1);
        float d = __shfl_down_sync(FULL, xc[j], 1);
        xl[j] = (lane == 0)  ? 0.f : u;
        xr[j] = (lane >= 27) ? 0.f : d;
    }

    // ---- landscape partial reductions (overlap with weight staging) ----
    #pragma unroll
    for (int br = 0; br < 2; br++) {
        const float* v = (br == 0 ? dtm1 : dtm2) + b * P784;
        float m1 = 1e30f, m2 = 1e30f, mx = -1e30f;
        for (int i = tid; i < P784; i += 128) {
            float f = v[i];
            mx = fmaxf(mx, f);
            if (f < m1) { m2 = m1; m1 = f; }
            else        { m2 = fminf(m2, f); }
        }
        #pragma unroll
        for (int o = 16; o > 0; o >>= 1) {
            float o1 = __shfl_down_sync(FULL, m1, o);
            float o2 = __shfl_down_sync(FULL, m2, o);
            float ox = __shfl_down_sync(FULL, mx, o);
            float nm1 = fminf(m1, o1);
            float nm2 = fminf(fmaxf(m1, o1), fminf(m2, o2));
            m1 = nm1; m2 = nm2; mx = fmaxf(mx, ox);
        }
        if (lane == 0) {
            part[br][wid][0] = m1; part[br][wid][1] = m2; part[br][wid][2] = mx;
        }
    }
    __syncthreads();   // weights + partials visible

    const float b2v = __ldg(b2g);
    float acc[7];
    #pragma unroll
    for (int i = 0; i < 7; i++) acc[i] = b2v;

    // ---- channel loop: all register/shuffle, no barriers ----
    #pragma unroll 1
    for (int ch = 0; ch < 32; ch++) {
        // conv1: 9 h1 rows (r0-1 .. r0+7) in registers
        float4 wa = *(const float4*)&w1t[ch][0];
        float4 wb = *(const float4*)&w1t[ch][4];
        float  w8 = w1t[ch][8];
        float  bc = w1t[ch][9];
        float h1[9];
        #pragma unroll
        for (int j = 0; j < 9; j++) {
            int row = r0 - 1 + j;
            float s = bc;
            s += xl[j    ] * wa.x + xc[j    ] * wa.y + xr[j    ] * wa.z;
            s += xl[j + 1] * wa.w + xc[j + 1] * wb.x + xr[j + 1] * wb.y;
            s += xl[j + 2] * wb.z + xc[j + 2] * wb.w + xr[j + 2] * w8;
            h1[j] = (row >= 0 && row < 28) ? fmaxf(s, 0.f) : 0.f;
        }

        // conv2: consume h1 rows with shuffled column halos
        float4 va = *(const float4*)&w2t[ch][0];
        float4 vb = *(const float4*)&w2t[ch][4];
        float  v8 = w2t[ch][8];
        float wv[9] = {va.x, va.y, va.z, va.w, vb.x, vb.y, vb.z, vb.w, v8};
        #pragma unroll
        for (int j = 0; j < 9; j++) {
            float hu = __shfl_up_sync  (FULL, h1[j], 1);
            float hd = __shfl_down_sync(FULL, h1[j], 1);
            float hl = (lane == 0)  ? 0.f : hu;
            float hr = (lane >= 27) ? 0.f : hd;
            #pragma unroll
            for (int dr = 0; dr < 3; dr++) {
                int i = j - dr;                 // output row index
                if (i >= 0 && i < 7) {
                    acc[i] += hl * wv[dr * 3 + 0]
                            + h1[j] * wv[dr * 3 + 1]
                            + hr * wv[dr * 3 + 2];
                }
            }
        }
    }

    // store conv branch output (relu)
    if (c < 28) {
        #pragma unroll
        for (int i = 0; i < 7; i++)
            g_cat[b * CATW + (r0 + i) * 28 + c] = fmaxf(acc[i], 0.f);
    }

    __syncthreads();   // landscape partials from all warps

    // tents: 128 threads -> Ls[2][64]
    {
        int br = tid >> 6, q = tid & 63;
        int k = q >> 5, ti = q & 31;
        float M1 = part[br][0][0], M2 = part[br][0][1], MX = part[br][0][2];
        #pragma unroll
        for (int w = 1; w < 4; w++) {
            float a1 = part[br][w][0], a2 = part[br][w][1], ax = part[br][w][2];
            float n1 = fminf(M1, a1);
            float n2 = fminf(fmaxf(M1, a1), fminf(M2, a2));
            M1 = n1; M2 = n2; MX = fmaxf(MX, ax);
        }
        float t0 = (br == 0) ? 0.01f : 0.05f;
        float dt = (br == 0) ? (0.28f / 31.0f) : (0.25f / 31.0f);
        float t  = t0 + (float)ti * dt;
        float vk = k ? M2 : M1;
        Ls[br][q] = fmaxf(0.f, fminf(t - vk, MX - t));
    }
    __syncthreads();

    // branch GEMMs: [64] @ [64,32] + bias, relu
    if (tid < 64) {
        int br = tid >> 5, f = tid & 31;
        const float* gw = br ? g2w : g1w;
        float s = br ? g2b[f] : g1b[f];
        #pragma unroll
        for (int j = 0; j < 64; j++) s += Ls[br][j] * gw[j * 32 + f];
        g_cat[b * CATW + 784 + br * 32 + f] = fmaxf(s, 0.f);
    }
}

// ---------------------------------------------------------------------------
// Kernel 2: fc1 split-K GEMM. [1024,848] @ [848,64] -> atomicAdd to g_zacc
//   grid = (16 m-tiles of 64) x (16 k-chunks of 53); 256 thr; 4x4 thread tiles.
// ---------------------------------------------------------------------------
__global__ void __launch_bounds__(256)
k_fc1(const float* __restrict__ W1)
{
    __shared__ __align__(16) float At[53 * 68];  // A^T: [k][m], stride 68
    __shared__ __align__(16) float Bs[53 * 64];  // [k][f]

    const int tid = threadIdx.x;
    const int m0  = blockIdx.x * 64;
    const int k0  = blockIdx.y * 53;
    const int tm  = tid & 15;
    const int tf  = tid >> 4;

    for (int e = tid; e < 53 * 64; e += 256) {
        int i = e / 53, j = e - i * 53;
        At[j * 68 + i] = g_cat[(m0 + i) * CATW + k0 + j];
    }
    for (int e = tid; e < 53 * 16; e += 256) {
        int j = e >> 4, q = e & 15;
        *(float4*)&Bs[j * 64 + q * 4] = *(const float4*)&W1[(k0 + j) * 64 + q * 4];
    }
    __syncthreads();

    float cacc[4][4] = {};
    #pragma unroll 4
    for (int k = 0; k < 53; k++) {
        float4 a  = *(const float4*)&At[k * 68 + tm * 4];
        float4 bb = *(const float4*)&Bs[k * 64 + tf * 4];
        float av[4] = {a.x, a.y, a.z, a.w};
        float bv[4] = {bb.x, bb.y, bb.z, bb.w};
        #pragma unroll
        for (int r = 0; r < 4; r++)
            #pragma unroll
            for (int q = 0; q < 4; q++)
                cacc[r][q] += av[r] * bv[q];
    }

    #pragma unroll
    for (int r = 0; r < 4; r++)
        #pragma unroll
        for (int q = 0; q < 4; q++)
            atomicAdd(&g_zacc[(m0 + tm * 4 + r) * 64 + tf * 4 + q], cacc[r][q]);
}

// ---------------------------------------------------------------------------
// Kernel 3: z = relu(zacc + b1); out = z @ W2 + b2.  32 blocks x 32 rows.
// ---------------------------------------------------------------------------
__global__ void __launch_bounds__(256)
k_fc2(const float* __restrict__ fc1b, const float* __restrict__ W2,
      const float* __restrict__ fc2b, float* __restrict__ out)
{
    __shared__ float zs[32 * 64];
    __shared__ float W2s[640];
    __shared__ float b2s[10];

    const int tid = threadIdx.x;
    const int m0  = blockIdx.x * 32;

    for (int e = tid; e < 32 * 64; e += 256) {
        int f = e & 63;
        zs[e] = fmaxf(g_zacc[m0 * 64 + e] + fc1b[f], 0.f);
    }
    for (int e = tid; e < 640; e += 256) W2s[e] = W2[e];
    if (tid < 10) b2s[tid] = fc2b[tid];
    __syncthreads();

    for (int e = tid; e < 320; e += 256) {
        int m = e / 10, cc = e - m * 10;
        float s = b2s[cc];
        #pragma unroll
        for (int f = 0; f < 64; f++) s += zs[m * 64 + f] * W2s[f * 10 + cc];
        out[(m0 + m) * 10 + cc] = s;
    }
}

// ---------------------------------------------------------------------------
extern "C" void kernel_launch(void* const* d_in, const int* in_sizes, int n_in,
                              void* d_out, int out_size)
{
    (void)in_sizes; (void)n_in; (void)out_size;
    const float* x    = (const float*)d_in[0];
    const float* dtm1 = (const float*)d_in[1];
    const float* dtm2 = (const float*)d_in[2];
    const float* w1   = (const float*)d_in[3];
    const float* b1   = (const float*)d_in[4];
    const float* w2   = (const float*)d_in[5];
    const float* b2   = (const float*)d_in[6];
    const float* g1w  = (const float*)d_in[7];
    const float* g1b  = (const float*)d_in[8];
    const float* g2w  = (const float*)d_in[9];
    const float* g2b  = (const float*)d_in[10];
    const float* fc1w = (const float*)d_in[11];
    const float* fc1b = (const float*)d_in[12];
    const float* fc2w = (const float*)d_in[13];
    const float* fc2b = (const float*)d_in[14];
    float* out = (float*)d_out;

    k_fused<<<BATCH, 128>>>(x, dtm1, dtm2, w1, b1, w2, b2, g1w, g1b, g2w, g2b);
    k_fc1<<<dim3(16, 16), 256>>>(fc1w);
    k_fc2<<<32, 256>>>(fc1b, fc2w, fc2b, out);
}

// round 11
// speedup vs baseline: 1.3365x; 1.0006x over previous
#include <cuda_runtime.h>
#include <cuda_bf16.h>

// Problem constants
#define BATCH    1024
#define P784     784
#define CATW     848            // 784 + 32 + 32

// Scratch (allocation-free rule: __device__ globals)
__device__ float g_cat [BATCH * CATW];   // [1024, 848] concat rows
__device__ float g_zacc[BATCH * 64];     // fc1 pre-activation accumulator

// ---------------------------------------------------------------------------
// Kernel 1: per-sample fused conv branch + landscape branches.
//   grid = 1024 blocks (1 per sample), 128 threads (4 warps).
//   Warp w owns output rows [7w, 7w+7); lane = column (lanes 28-31 idle).
//   conv1 -> h1 kept entirely in REGISTERS (9 rows per thread, redundancy 9/7);
//   conv2 column halos come from warp shuffles. No smem tile, no per-channel
//   barriers.
//   landscape: tent(v,t) monotone non-increasing in v => top-2 tents come from
//   the two SMALLEST filtration values; only (min1, min2, max) needed.
// ---------------------------------------------------------------------------
__global__ void __launch_bounds__(128)
k_fused(const float* __restrict__ x,
        const float* __restrict__ dtm1,
        const float* __restrict__ dtm2,
        const float* __restrict__ w1g, const float* __restrict__ b1g,
        const float* __restrict__ w2g, const float* __restrict__ b2g,
        const float* __restrict__ g1w, const float* __restrict__ g1b,
        const float* __restrict__ g2w, const float* __restrict__ g2b)
{
    __shared__ __align__(16) float w1t[32][12];   // [ch][tap0..8, 9=bias]
    __shared__ __align__(16) float w2t[32][12];   // [ch][tap0..8]
    __shared__ float part[2][4][3];               // branch, warp, (m1,m2,mx)
    __shared__ float Ls[2][64];                   // landscapes

    const int tid  = threadIdx.x;
    const int b    = blockIdx.x;
    const int wid  = tid >> 5;
    const int lane = tid & 31;
    const unsigned FULL = 0xffffffffu;

    // zero fc1 accumulator row (consumed by k_fc1)
    if (tid >= 64) g_zacc[b * 64 + (tid - 64)] = 0.f;

    // stage weights transposed: taps contiguous per channel
    for (int i = tid; i < 288; i += 128) {
        int tap = i / 32, c = i % 32;
        w1t[c][tap] = w1g[i];
        w2t[c][tap] = w2g[i];
    }
    if (tid < 32) w1t[tid][9] = b1g[tid];

    // ---- load input rows into registers (rows r0-2 .. r0+8, zero-padded) ----
    const int r0 = wid * 7;
    const int c  = lane;
    float xc[11], xl[11], xr[11];
    #pragma unroll
    for (int j = 0; j < 11; j++) {
        int row = r0 - 2 + j;
        float v = 0.f;
        if (row >= 0 && row < 28 && c < 28) v = x[b * P784 + row * 28 + c];
        xc[j] = v;
    }
    #pragma unroll
    for (int j = 0; j < 11; j++) {
        float u = __shfl_up_sync  (FULL, xc[j], 1);
        float d = __shfl_down_sync(FULL, xc[j], 1);
        xl[j] = (lane == 0)  ? 0.f : u;
        xr[j] = (lane >= 27) ? 0.f : d;
    }

    // ---- landscape partial reductions (overlap with weight staging) ----
    #pragma unroll
    for (int br = 0; br < 2; br++) {
        const float* v = (br == 0 ? dtm1 : dtm2) + b * P784;
        float m1 = 1e30f, m2 = 1e30f, mx = -1e30f;
        for (int i = tid; i < P784; i += 128) {
            float f = v[i];
            mx = fmaxf(mx, f);
            if (f < m1) { m2 = m1; m1 = f; }
            else        { m2 = fminf(m2, f); }
        }
        #pragma unroll
        for (int o = 16; o > 0; o >>= 1) {
            float o1 = __shfl_down_sync(FULL, m1, o);
            float o2 = __shfl_down_sync(FULL, m2, o);
            float ox = __shfl_down_sync(FULL, mx, o);
            float nm1 = fminf(m1, o1);
            float nm2 = fminf(fmaxf(m1, o1), fminf(m2, o2));
            m1 = nm1; m2 = nm2; mx = fmaxf(mx, ox);
        }
        if (lane == 0) {
            part[br][wid][0] = m1; part[br][wid][1] = m2; part[br][wid][2] = mx;
        }
    }
    __syncthreads();   // weights + partials visible

    const float b2v = __ldg(b2g);
    float acc[7];
    #pragma unroll
    for (int i = 0; i < 7; i++) acc[i] = b2v;

    // ---- channel loop: all register/shuffle, no barriers ----
    #pragma unroll 1
    for (int ch = 0; ch < 32; ch++) {
        // conv1: 9 h1 rows (r0-1 .. r0+7) in registers
        float4 wa = *(const float4*)&w1t[ch][0];
        float4 wb = *(const float4*)&w1t[ch][4];
        float  w8 = w1t[ch][8];
        float  bc = w1t[ch][9];
        float h1[9];
        #pragma unroll
        for (int j = 0; j < 9; j++) {
            int row = r0 - 1 + j;
            float s = bc;
            s += xl[j    ] * wa.x + xc[j    ] * wa.y + xr[j    ] * wa.z;
            s += xl[j + 1] * wa.w + xc[j + 1] * wb.x + xr[j + 1] * wb.y;
            s += xl[j + 2] * wb.z + xc[j + 2] * wb.w + xr[j + 2] * w8;
            h1[j] = (row >= 0 && row < 28) ? fmaxf(s, 0.f) : 0.f;
        }

        // conv2: consume h1 rows with shuffled column halos
        float4 va = *(const float4*)&w2t[ch][0];
        float4 vb = *(const float4*)&w2t[ch][4];
        float  v8 = w2t[ch][8];
        float wv[9] = {va.x, va.y, va.z, va.w, vb.x, vb.y, vb.z, vb.w, v8};
        #pragma unroll
        for (int j = 0; j < 9; j++) {
            float hu = __shfl_up_sync  (FULL, h1[j], 1);
            float hd = __shfl_down_sync(FULL, h1[j], 1);
            float hl = (lane == 0)  ? 0.f : hu;
            float hr = (lane >= 27) ? 0.f : hd;
            #pragma unroll
            for (int dr = 0; dr < 3; dr++) {
                int i = j - dr;                 // output row index
                if (i >= 0 && i < 7) {
                    acc[i] += hl * wv[dr * 3 + 0]
                            + h1[j] * wv[dr * 3 + 1]
                            + hr * wv[dr * 3 + 2];
                }
            }
        }
    }

    // store conv branch output (relu)
    if (c < 28) {
        #pragma unroll
        for (int i = 0; i < 7; i++)
            g_cat[b * CATW + (r0 + i) * 28 + c] = fmaxf(acc[i], 0.f);
    }

    __syncthreads();   // landscape partials from all warps

    // tents: 128 threads -> Ls[2][64]
    {
        int br = tid >> 6, q = tid & 63;
        int k = q >> 5, ti = q & 31;
        float M1 = part[br][0][0], M2 = part[br][0][1], MX = part[br][0][2];
        #pragma unroll
        for (int w = 1; w < 4; w++) {
            float a1 = part[br][w][0], a2 = part[br][w][1], ax = part[br][w][2];
            float n1 = fminf(M1, a1);
            float n2 = fminf(fmaxf(M1, a1), fminf(M2, a2));
            M1 = n1; M2 = n2; MX = fmaxf(MX, ax);
        }
        float t0 = (br == 0) ? 0.01f : 0.05f;
        float dt = (br == 0) ? (0.28f / 31.0f) : (0.25f / 31.0f);
        float t  = t0 + (float)ti * dt;
        float vk = k ? M2 : M1;
        Ls[br][q] = fmaxf(0.f, fminf(t - vk, MX - t));
    }
    __syncthreads();

    // branch GEMMs: [64] @ [64,32] + bias, relu
    if (tid < 64) {
        int br = tid >> 5, f = tid & 31;
        const float* gw = br ? g2w : g1w;
        float s = br ? g2b[f] : g1b[f];
        #pragma unroll
        for (int j = 0; j < 64; j++) s += Ls[br][j] * gw[j * 32 + f];
        g_cat[b * CATW + 784 + br * 32 + f] = fmaxf(s, 0.f);
    }
}

// ---------------------------------------------------------------------------
// Kernel 2: fc1 split-K GEMM. [1024,848] @ [848,64] -> atomicAdd to g_zacc
//   grid = (16 m-tiles of 64) x (16 k-chunks of 53); 256 thr; 4x4 thread tiles.
// ---------------------------------------------------------------------------
__global__ void __launch_bounds__(256)
k_fc1(const float* __restrict__ W1)
{
    __shared__ __align__(16) float At[53 * 68];  // A^T: [k][m], stride 68
    __shared__ __align__(16) float Bs[53 * 64];  // [k][f]

    const int tid = threadIdx.x;
    const int m0  = blockIdx.x * 64;
    const int k0  = blockIdx.y * 53;
    const int tm  = tid & 15;
    const int tf  = tid >> 4;

    for (int e = tid; e < 53 * 64; e += 256) {
        int i = e / 53, j = e - i * 53;
        At[j * 68 + i] = g_cat[(m0 + i) * CATW + k0 + j];
    }
    for (int e = tid; e < 53 * 16; e += 256) {
        int j = e >> 4, q = e & 15;
        *(float4*)&Bs[j * 64 + q * 4] = *(const float4*)&W1[(k0 + j) * 64 + q * 4];
    }
    __syncthreads();

    float cacc[4][4] = {};
    #pragma unroll 4
    for (int k = 0; k < 53; k++) {
        float4 a  = *(const float4*)&At[k * 68 + tm * 4];
        float4 bb = *(const float4*)&Bs[k * 64 + tf * 4];
        float av[4] = {a.x, a.y, a.z, a.w};
        float bv[4] = {bb.x, bb.y, bb.z, bb.w};
        #pragma unroll
        for (int r = 0; r < 4; r++)
            #pragma unroll
            for (int q = 0; q < 4; q++)
                cacc[r][q] += av[r] * bv[q];
    }

    #pragma unroll
    for (int r = 0; r < 4; r++)
        #pragma unroll
        for (int q = 0; q < 4; q++)
            atomicAdd(&g_zacc[(m0 + tm * 4 + r) * 64 + tf * 4 + q], cacc[r][q]);
}

// ---------------------------------------------------------------------------
// Kernel 3: z = relu(zacc + b1); out = z @ W2 + b2.  32 blocks x 32 rows.
// ---------------------------------------------------------------------------
__global__ void __launch_bounds__(256)
k_fc2(const float* __restrict__ fc1b, const float* __restrict__ W2,
      const float* __restrict__ fc2b, float* __restrict__ out)
{
    __shared__ float zs[32 * 64];
    __shared__ float W2s[640];
    __shared__ float b2s[10];

    const int tid = threadIdx.x;
    const int m0  = blockIdx.x * 32;

    for (int e = tid; e < 32 * 64; e += 256) {
        int f = e & 63;
        zs[e] = fmaxf(g_zacc[m0 * 64 + e] + fc1b[f], 0.f);
    }
    for (int e = tid; e < 640; e += 256) W2s[e] = W2[e];
    if (tid < 10) b2s[tid] = fc2b[tid];
    __syncthreads();

    for (int e = tid; e < 320; e += 256) {
        int m = e / 10, cc = e - m * 10;
        float s = b2s[cc];
        #pragma unroll
        for (int f = 0; f < 64; f++) s += zs[m * 64 + f] * W2s[f * 10 + cc];
        out[(m0 + m) * 10 + cc] = s;
    }
}

// ---------------------------------------------------------------------------
extern "C" void kernel_launch(void* const* d_in, const int* in_sizes, int n_in,
                              void* d_out, int out_size)
{
    (void)in_sizes; (void)n_in; (void)out_size;
    const float* x    = (const float*)d_in[0];
    const float* dtm1 = (const float*)d_in[1];
    const float* dtm2 = (const float*)d_in[2];
    const float* w1   = (const float*)d_in[3];
    const float* b1   = (const float*)d_in[4];
    const float* w2   = (const float*)d_in[5];
    const float* b2   = (const float*)d_in[6];
    const float* g1w  = (const float*)d_in[7];
    const float* g1b  = (const float*)d_in[8];
    const float* g2w  = (const float*)d_in[9];
    const float* g2b  = (const float*)d_in[10];
    const float* fc1w = (const float*)d_in[11];
    const float* fc1b = (const float*)d_in[12];
    const float* fc2w = (const float*)d_in[13];
    const float* fc2b = (const float*)d_in[14];
    float* out = (float*)d_out;

    k_fused<<<BATCH, 128>>>(x, dtm1, dtm2, w1, b1, w2, b2, g1w, g1b, g2w, g2b);
    k_fc1<<<dim3(16, 16), 256>>>(fc1w);
    k_fc2<<<32, 256>>>(fc1b, fc2w, fc2b, out);
}